// round 16
// baseline (speedup 1.0000x reference)
#include <cuda_runtime.h>
#include <cuda_bf16.h>
#include <cuda.h>
#include <stdint.h>

#define NB 16
#define TQ 2048
#define TK 2048
#define DD 1024

#if defined(__CUDA_ARCH__) && defined(__CUDA_ARCH_FEAT_SM103_ALL)
#define HAS_TCGEN05 1
#else
#define HAS_TCGEN05 0
#endif

// ---------------- scratch (static __device__ arrays; no runtime alloc) ----
__device__ float         g_scores[(size_t)NB * TQ * TK];    // masked logits
__device__ __nv_bfloat16 g_qs[2][(size_t)NB * TQ * DD];     // q hi/lo       [b][tq][d]
__device__ __nv_bfloat16 g_ks[2][(size_t)NB * TK * DD];     // k^T hi/lo     [b][tk][d]
__device__ __nv_bfloat16 g_vt[2][(size_t)NB * DD * TK];     // v^T hi/lo     [b][d][tk]
__device__ __nv_bfloat16 g_p [2][(size_t)NB * TQ * TK];     // softmax hi/lo [b][tq][tk]

__device__ __forceinline__ uint32_t smem_u32(const void* p) {
    uint32_t a;
    asm("{ .reg .u64 t; cvta.to.shared.u64 t, %1; cvt.u32.u64 %0, t; }" : "=r"(a) : "l"(p));
    return a;
}

#define MASK_BYTES 0
#define MASK_WORDS 1
__device__ __forceinline__ int detect_mask_kind(const void* mask) {
    const uint32_t* w = (const uint32_t*)mask;
    bool all01 = true, all0f = true;
    #pragma unroll 8
    for (int i = 0; i < 64; ++i) {
        uint32_t x = w[i];
        all01 &= (x <= 1u);
        all0f &= (x == 0u || x == 0x3F800000u);
    }
    return (all01 || all0f) ? MASK_WORDS : MASK_BYTES;
}

__device__ __forceinline__ void split2(float x, __nv_bfloat16& a0, __nv_bfloat16& a1) {
    a0 = __float2bfloat16(x);
    a1 = __float2bfloat16(x - __bfloat162float(a0));
}

// ---------------- sm_103a-only PTX wrappers --------------------------------
#if HAS_TCGEN05
__device__ __forceinline__ uint32_t elect_one() {
    uint32_t pred;
    asm volatile("{ .reg .pred p; elect.sync _|p, 0xFFFFFFFF; selp.b32 %0, 1, 0, p; }" : "=r"(pred));
    return pred;
}
__device__ __forceinline__ uint32_t ctarank() {
    uint32_t r; asm("mov.u32 %0, %%cluster_ctarank;" : "=r"(r)); return r;
}
#define TCG_ALLOC(sa, n)  asm volatile("tcgen05.alloc.cta_group::1.sync.aligned.shared::cta.b32 [%0], %1;" :: "r"(sa), "r"(n) : "memory")
#define TCG_DEALLOC(t, n) asm volatile("tcgen05.dealloc.cta_group::1.sync.aligned.b32 %0, %1;" :: "r"(t), "r"(n))
#define TCG_RELINQ()      asm volatile("tcgen05.relinquish_alloc_permit.cta_group::1.sync.aligned;")
#define TCG_COMMIT(mb)    asm volatile("tcgen05.commit.cta_group::1.mbarrier::arrive::one.shared::cluster.b64 [%0];" :: "r"(mb) : "memory")
#define TCG_FENCE_AFTER()  asm volatile("tcgen05.fence::after_thread_sync;" ::: "memory")
#define TCG_FENCE_BEFORE() asm volatile("tcgen05.fence::before_thread_sync;" ::: "memory")
#define TCG_WAIT_LD()      asm volatile("tcgen05.wait::ld.sync.aligned;" ::: "memory")
#define MBAR_INIT(mb, n)   asm volatile("mbarrier.init.shared.b64 [%0], %1;" :: "r"(mb), "r"(n) : "memory")
#define MBAR_INVAL(mb)     asm volatile("mbarrier.inval.shared.b64 [%0];" :: "r"(mb) : "memory")
#define MBAR_ARRIVE(mb)    asm volatile("mbarrier.arrive.shared.b64 _, [%0];" :: "r"(mb) : "memory")
#define MBAR_ARRIVE_CLUSTER(mb, r)                                           \
    asm volatile("{ .reg .b32 ra; mapa.shared::cluster.u32 ra, %0, %1;\n\t"  \
                 "mbarrier.arrive.shared::cluster.b64 _, [ra]; }"            \
                 :: "r"(mb), "r"(r) : "memory")
#define MBAR_EXPECT_TX(mb, n) asm volatile("mbarrier.arrive.expect_tx.shared.b64 _, [%0], %1;" :: "r"(mb), "r"(n) : "memory")
#define FENCE_ASYNC_SHARED() asm volatile("fence.proxy.async.shared::cta;" ::: "memory")
#define CLUSTER_SYNC() do {                                                  \
    asm volatile("barrier.cluster.arrive.aligned;" ::: "memory");            \
    asm volatile("barrier.cluster.wait.aligned;" ::: "memory");              \
} while (0)

#define TMA_LOAD_2D(smem, map, x, y, mbar)                                   \
    asm volatile("cp.async.bulk.tensor.2d.shared::cta.global.tile.mbarrier::complete_tx::bytes " \
                 "[%0], [%1, {%2, %3}], [%4];"                               \
                 :: "r"(smem), "l"(map), "r"(x), "r"(y), "r"(mbar) : "memory")

#define TMA_LOAD_2D_MC(smem, map, x, y, mbar, msk)                           \
    asm volatile("cp.async.bulk.tensor.2d.shared::cluster.global.tile.mbarrier::complete_tx::bytes.multicast::cluster " \
                 "[%0], [%1, {%2, %3}], [%4], %5;"                           \
                 :: "r"(smem), "l"(map), "r"(x), "r"(y), "r"(mbar), "h"((uint16_t)(msk)) : "memory")

#define MBAR_WAIT(mb, par) do {                                              \
    uint32_t _m = (mb), _p = (par), _d;                                      \
    asm volatile("{ .reg .pred p; mbarrier.try_wait.parity.acquire.cta.shared::cta.b64 p, [%1], %2; selp.b32 %0,1,0,p; }" \
                 : "=r"(_d) : "r"(_m), "r"(_p) : "memory");                  \
    if (!_d) {                                                               \
        asm volatile("{ .reg .pred P1; WL_%=: mbarrier.try_wait.parity.acquire.cta.shared::cta.b64 P1, [%0], %1, 0x989680; \n\t" \
                     "@P1 bra.uni WD_%=; bra.uni WL_%=; WD_%=: }"            \
                     :: "r"(_m), "r"(_p) : "memory");                        \
    }                                                                        \
} while (0)

#define TCG_LD_X32(r, ta)                                                    \
    asm volatile("tcgen05.ld.sync.aligned.32x32b.x32.b32 "                   \
        "{%0,%1,%2,%3,%4,%5,%6,%7,%8,%9,%10,%11,%12,%13,%14,%15,"            \
        "%16,%17,%18,%19,%20,%21,%22,%23,%24,%25,%26,%27,%28,%29,%30,%31}, [%32];" \
        : "=r"((r)[0]),"=r"((r)[1]),"=r"((r)[2]),"=r"((r)[3]),               \
          "=r"((r)[4]),"=r"((r)[5]),"=r"((r)[6]),"=r"((r)[7]),               \
          "=r"((r)[8]),"=r"((r)[9]),"=r"((r)[10]),"=r"((r)[11]),             \
          "=r"((r)[12]),"=r"((r)[13]),"=r"((r)[14]),"=r"((r)[15]),           \
          "=r"((r)[16]),"=r"((r)[17]),"=r"((r)[18]),"=r"((r)[19]),           \
          "=r"((r)[20]),"=r"((r)[21]),"=r"((r)[22]),"=r"((r)[23]),           \
          "=r"((r)[24]),"=r"((r)[25]),"=r"((r)[26]),"=r"((r)[27]),           \
          "=r"((r)[28]),"=r"((r)[29]),"=r"((r)[30]),"=r"((r)[31])            \
        : "r"(ta))

__device__ __forceinline__ void mma_f16_ss(uint32_t d_tmem, uint64_t a_desc,
                                           uint64_t b_desc, uint32_t idesc,
                                           uint32_t enable_d) {
    asm volatile(
        "{\n\t.reg .pred p;\n\tsetp.ne.u32 p, %5, 0;\n\t"
        "tcgen05.mma.cta_group::1.kind::f16 [%0], %1, %2, %3, {%4, %4, %4, %4}, p;\n\t}"
        :: "r"(d_tmem), "l"(a_desc), "l"(b_desc), "r"(idesc), "r"(0u), "r"(enable_d)
        : "memory");
}

static constexpr uint64_t DESC_BASE_SW128 =
    (uint64_t(2) << 61) | (uint64_t(1) << 46) | (uint64_t(64) << 32) | (uint64_t(1) << 16);
__device__ __forceinline__ uint64_t mk_desc(uint32_t addr) {
    return DESC_BASE_SW128 | ((uint64_t)(addr >> 4) & 0x3FFF);
}
#endif // HAS_TCGEN05

// idesc: dtype F32, atype/btype BF16, N=128, M=128 (validated formula)
static constexpr uint32_t IDESC_128x128 =
    (1u << 4) | (1u << 7) | (1u << 10) | ((128u / 8) << 17) | ((128u / 16) << 24);

// ---------------- conversion pre-passes ------------------------------------
__global__ __launch_bounds__(256) void split_q_kernel(const float* __restrict__ q) {
    size_t i = ((size_t)blockIdx.x * 256 + threadIdx.x) * 4;
    float4 x = *reinterpret_cast<const float4*>(q + i);
    __nv_bfloat16 a0[4], a1[4];
    split2(x.x, a0[0], a1[0]);
    split2(x.y, a0[1], a1[1]);
    split2(x.z, a0[2], a1[2]);
    split2(x.w, a0[3], a1[3]);
    *reinterpret_cast<uint2*>(&g_qs[0][i]) = *reinterpret_cast<uint2*>(a0);
    *reinterpret_cast<uint2*>(&g_qs[1][i]) = *reinterpret_cast<uint2*>(a1);
}

// k[b][d][t] -> g_ks[s][b][t][d]
__global__ __launch_bounds__(256) void tsplit_k_kernel(const float* __restrict__ k) {
    __shared__ float tile[32][33];
    const int b = blockIdx.z, d0 = blockIdx.y * 32, t0 = blockIdx.x * 32;
    const int tx = threadIdx.x, ty = threadIdx.y;
    const float* src = k + ((size_t)b * DD + d0) * TK + t0;
    #pragma unroll
    for (int j = 0; j < 32; j += 8) tile[ty + j][tx] = src[(size_t)(ty + j) * TK + tx];
    __syncthreads();
    const size_t obase = ((size_t)b * TK + t0) * DD + d0;
    #pragma unroll
    for (int j = 0; j < 32; j += 8) {
        float x = tile[tx][ty + j];
        __nv_bfloat16 a0, a1;
        split2(x, a0, a1);
        size_t o = obase + (size_t)(ty + j) * DD + tx;
        g_ks[0][o] = a0; g_ks[1][o] = a1;
    }
}

// v[b][t][d] -> g_vt[s][b][d][t]
__global__ __launch_bounds__(256) void tsplit_v_kernel(const float* __restrict__ v) {
    __shared__ float tile[32][33];
    const int b = blockIdx.z, d0 = blockIdx.x * 32, t0 = blockIdx.y * 32;
    const int tx = threadIdx.x, ty = threadIdx.y;
    const float* src = v + ((size_t)b * TK + t0) * DD + d0;
    #pragma unroll
    for (int j = 0; j < 32; j += 8) tile[ty + j][tx] = src[(size_t)(ty + j) * DD + tx];
    __syncthreads();
    const size_t obase = ((size_t)b * DD + d0) * TK + t0;
    #pragma unroll
    for (int j = 0; j < 32; j += 8) {
        float x = tile[tx][ty + j];
        __nv_bfloat16 a0, a1;
        split2(x, a0, a1);
        size_t o = obase + (size_t)(ty + j) * TK + tx;
        g_vt[0][o] = a0; g_vt[1][o] = a1;
    }
}

// ---------------- persistent cluster-multicast tcgen05 GEMM ----------------
// MODE 0: scores = q @ k^T (2x2 split, 4 terms) + mask -> g_scores (fp32)
// MODE 1: out    = P @ v^T (2x2 split, 3 terms)        -> d_out (fp32)
//
// 148 persistent CTAs in 74 clusters of 2. Cluster ci processes pair-tiles
// pt = ci + it*74; ranks 0/1 take y = 2*yp + rank (same B panel). B is fed
// by ONE multicast TMA per slot (rank 0 issues), halving B-side L2 traffic
// (feed was the R15 limiter: floor pace needs 11.9 TB/s unicast > LTS cap).
// Release protocol per slot: each rank waits local mmaB commit ->
// expect_tx local fullB -> cluster-arrive rank0's bFree (count 2); rank0
// waits bFree -> multicast fill. TMEM double-buffered; warps 4-11 drain the
// epilogue while warp 0 runs the next tile's MMAs (from R15).
template<int MODE>
__global__ __launch_bounds__(384, 1) __cluster_dims__(2, 1, 1)
void mma_gemm_kernel(const __grid_constant__ CUtensorMap ta0,
                     const __grid_constant__ CUtensorMap ta1,
                     const __grid_constant__ CUtensorMap tb0,
                     const __grid_constant__ CUtensorMap tb1,
                     const void* __restrict__ mask, float* __restrict__ Zout)
{
#if HAS_TCGEN05
    constexpr int NP     = (MODE == 0) ? 4 : 3;
    constexpr int KTOT   = (MODE == 0) ? DD : TK;
    constexpr int NCH    = KTOT / 64;
    constexpr int NST    = 2 * NCH;
    constexpr int LDC    = (MODE == 0) ? TK : DD;
    constexpr int RB     = (MODE == 0) ? TK : DD;
    constexpr int LOG_NX = (MODE == 0) ? 3 : 2;            // x-tiles = 8 / 4
    constexpr int NPAIR  = NB * 8 * ((MODE == 0) ? 8 : 4); // y-pairs x x-tiles x batch
    constexpr uint32_t SSZ  = 32768u;
    constexpr uint32_t AOFF = 4u * SSZ;

    const int PA[4] = {0, 0, 1, 1};
    const int PB[4] = {0, 1, 0, 1};

    extern __shared__ char dsm[];
    __shared__ uint64_t s_mbar[19]; // fullB[4] mmaB[4] fullA[3] tileDone[2] epiDone[2] bFree[4]
    __shared__ uint32_t s_tmem;
    __shared__ int      s_mkind;

    const int tid = threadIdx.x;
    const int wid = tid >> 5, lid = tid & 31;
    const int rank = (int)ctarank();
    const int ci  = blockIdx.x >> 1;                       // cluster index
    const int G2  = gridDim.x >> 1;                        // clusters (74)
    const int nt  = (NPAIR - ci + G2 - 1) / G2;            // tiles per CTA

    const uint32_t su   = smem_u32(dsm);
    const uint32_t pad  = (1024u - (su & 1023u)) & 1023u;
    const uint32_t sb_u = su + pad;

    uint32_t fullB_[4], mmaB_[4], fullA_[3], tileDone_[2], epiDone_[2], bFree_[4];
    #pragma unroll
    for (int i = 0; i < 4; ++i) { fullB_[i] = smem_u32(&s_mbar[i]); mmaB_[i] = smem_u32(&s_mbar[4 + i]); }
    #pragma unroll
    for (int i = 0; i < 3; ++i) fullA_[i] = smem_u32(&s_mbar[8 + i]);
    #pragma unroll
    for (int i = 0; i < 2; ++i) { tileDone_[i] = smem_u32(&s_mbar[11 + i]); epiDone_[i] = smem_u32(&s_mbar[13 + i]); }
    #pragma unroll
    for (int i = 0; i < 4; ++i) bFree_[i] = smem_u32(&s_mbar[15 + i]);

    if (wid == 0) TCG_ALLOC(smem_u32(&s_tmem), 512);
    if (tid == 0) {
        #pragma unroll
        for (int i = 0; i < 13; ++i) MBAR_INIT(smem_u32(&s_mbar[i]), 1);
        MBAR_INIT(epiDone_[0], 8);
        MBAR_INIT(epiDone_[1], 8);
        #pragma unroll
        for (int i = 0; i < 4; ++i) MBAR_INIT(bFree_[i], 2);
        FENCE_ASYNC_SHARED();
        if (MODE == 0) s_mkind = detect_mask_kind(mask);
        // initial expect_tx for the 4 multicast B fills (phase 0)
        #pragma unroll
        for (int i = 0; i < 4; ++i) MBAR_EXPECT_TX(fullB_[i], SSZ);
    }
    __syncthreads();
    CLUSTER_SYNC();                     // both CTAs' barriers + expect_tx visible
    const uint32_t tmem = s_tmem;

    if (wid == 1 && elect_one()) {
        // ====================== producer warp ======================
        // tile-0 coordinates
        const int x0 = ci & ((1 << LOG_NX) - 1);
        const int yp0 = (ci >> LOG_NX) & 7, b0 = ci >> (LOG_NX + 3);
        const int rA0 = b0 * TQ + (yp0 * 2 + rank) * 128;
        const int rB0 = b0 * RB + x0 * 256;

        // A prologue (local, 3 chunks)
        #pragma unroll
        for (int j = 0; j < 3; ++j) {
            const uint32_t sa = sb_u + AOFF + j * SSZ;
            MBAR_EXPECT_TX(fullA_[j], SSZ);
            TMA_LOAD_2D(sa,           &ta0, j * 64, rA0, fullA_[j]);
            TMA_LOAD_2D(sa + 16384u,  &ta1, j * 64, rA0, fullA_[j]);
        }
        // B prologue: rank 0 multicasts 4 slots (steps 0..3 of tile 0)
        if (rank == 0) {
            #pragma unroll
            for (int i = 0; i < 4; ++i) {
                const uint32_t sbb = sb_u + i * SSZ;
                TMA_LOAD_2D_MC(sbb,          &tb0, (i >> 1) * 64, rB0 + (i & 1) * 128, fullB_[i], 3);
                TMA_LOAD_2D_MC(sbb + 16384u, &tb1, (i >> 1) * 64, rB0 + (i & 1) * 128, fullB_[i], 3);
            }
        }

        const int NSTtot = nt * NST;
        const int NCHtot = nt * NCH;
        for (int S2 = 0; S2 < NSTtot - 4; ++S2) {
            const int sl = S2 & 3, pr = (S2 >> 2) & 1;
            MBAR_WAIT(mmaB_[sl], pr);             // local MMAs done with slot
            MBAR_EXPECT_TX(fullB_[sl], SSZ);      // arm local barrier for refill
            MBAR_ARRIVE_CLUSTER(bFree_[sl], 0);   // report release to leader
            if (rank == 0) {
                MBAR_WAIT(bFree_[sl], pr);        // both ranks released
                const int Sg = S2 + 4;
                const int it = Sg / NST, s = Sg % NST;
                const int t = ci + it * G2;
                const int x = t & ((1 << LOG_NX) - 1);
                const int bb = t >> (LOG_NX + 3);
                const int rBv = bb * RB + x * 256 + (s & 1) * 128;
                const uint32_t dst = sb_u + (uint32_t)sl * SSZ;
                TMA_LOAD_2D_MC(dst,          &tb0, (s >> 1) * 64, rBv, fullB_[sl], 3);
                TMA_LOAD_2D_MC(dst + 16384u, &tb1, (s >> 1) * 64, rBv, fullB_[sl], 3);
            }
            if ((S2 & 1) == 1) {                  // A refill (local)
                const int Cg = (S2 >> 1) + 3;
                if (Cg < NCHtot) {
                    const int it = Cg / NCH, cl = Cg % NCH;
                    const int t = ci + it * G2;
                    const int yp = (t >> LOG_NX) & 7, bb = t >> (LOG_NX + 3);
                    const int rAv = bb * TQ + (yp * 2 + rank) * 128;
                    const uint32_t dst = sb_u + AOFF + (uint32_t)(Cg % 3) * SSZ;
                    MBAR_EXPECT_TX(fullA_[Cg % 3], SSZ);
                    TMA_LOAD_2D(dst,           &ta0, cl * 64, rAv, fullA_[Cg % 3]);
                    TMA_LOAD_2D(dst + 16384u,  &ta1, cl * 64, rAv, fullA_[Cg % 3]);
                }
            }
        }
    }

    if (wid == 0 && elect_one()) {
        // ====================== MMA consumer warp ======================
        for (int it = 0; it < nt; ++it) {
            const uint32_t dOff = (uint32_t)(it & 1) * 256u;
            if (it >= 2) MBAR_WAIT(epiDone_[it & 1], ((it >> 1) - 1) & 1);
            for (int s = 0; s < NST; ++s) {
                const int c = s >> 1, h = s & 1;
                const int Sg = it * NST + s;
                const int Cg = it * NCH + c;
                const uint32_t aBase = sb_u + AOFF + (uint32_t)(Cg % 3) * SSZ;
                const uint32_t bBase = sb_u + (uint32_t)(Sg & 3) * SSZ;

                if (h == 0) MBAR_WAIT(fullA_[Cg % 3], (Cg / 3) & 1);
                MBAR_WAIT(fullB_[Sg & 3], (Sg >> 2) & 1);

                #pragma unroll
                for (int pi = 0; pi < NP; ++pi) {
                    const uint64_t ad = mk_desc(aBase + (uint32_t)PA[pi] * 16384u);
                    const uint64_t bd = mk_desc(bBase + (uint32_t)PB[pi] * 16384u);
                    #pragma unroll
                    for (int g = 0; g < 4; ++g)
                        mma_f16_ss(tmem + dOff + h * 128, ad + 2 * g, bd + 2 * g,
                                   IDESC_128x128, !(c == 0 && pi == 0 && g == 0));
                }
                TCG_COMMIT(mmaB_[Sg & 3]);
            }
            TCG_COMMIT(tileDone_[it & 1]);
        }
    }

    if (wid >= 4) {
        // ====================== epilogue warps (8) ======================
        const int row  = (wid & 3) * 32 + lid;
        const int coff = ((wid >> 2) - 1) * 128;
        const int mkind = (MODE == 0) ? s_mkind : 0;

        for (int it = 0; it < nt; ++it) {
            const uint32_t dOff = (uint32_t)(it & 1) * 256u;
            MBAR_WAIT(tileDone_[it & 1], (it >> 1) & 1);
            TCG_FENCE_AFTER();

            const int t = ci + it * G2;
            const int x = t & ((1 << LOG_NX) - 1);
            const int yp = (t >> LOG_NX) & 7, bb = t >> (LOG_NX + 3);
            const int mBase = (yp * 2 + rank) * 128, nBase = x * 256;

            float* C = (MODE == 0) ? (g_scores + (size_t)bb * TQ * TK)
                                   : (Zout + (size_t)bb * TQ * DD);
            const size_t crow = (size_t)(mBase + row) * LDC + nBase + coff;
            const size_t erow = (MODE == 0)
                ? (((size_t)bb * TQ + mBase + row) * TK + nBase + coff) : 0;

            #pragma unroll
            for (int cc = 0; cc < 4; ++cc) {
                uint32_t r[32];
                TCG_LD_X32(r, tmem + dOff + coff + cc * 32);
                TCG_WAIT_LD();
                #pragma unroll
                for (int g = 0; g < 4; ++g) {
                    float vals[8];
                    #pragma unroll
                    for (int j = 0; j < 8; ++j) vals[j] = __uint_as_float(r[g * 8 + j]);
                    const int col = cc * 32 + g * 8;
                    if (MODE == 0) {
                        const size_t eidx = erow + col;
                        bool mk[8];
                        if (mkind == MASK_BYTES) {
                            unsigned long long mv =
                                *reinterpret_cast<const unsigned long long*>((const uint8_t*)mask + eidx);
                            #pragma unroll
                            for (int j = 0; j < 8; ++j) mk[j] = ((mv >> (8 * j)) & 0xffULL) != 0;
                        } else {
                            const uint32_t* mw = (const uint32_t*)mask + eidx;
                            uint4 w0 = *reinterpret_cast<const uint4*>(mw);
                            uint4 w1 = *reinterpret_cast<const uint4*>(mw + 4);
                            mk[0] = w0.x != 0; mk[1] = w0.y != 0; mk[2] = w0.z != 0; mk[3] = w0.w != 0;
                            mk[4] = w1.x != 0; mk[5] = w1.y != 0; mk[6] = w1.z != 0; mk[7] = w1.w != 0;
                        }
                        #pragma unroll
                        for (int j = 0; j < 8; ++j)
                            if (mk[j]) vals[j] = -1.0e9f;
                    }
                    *reinterpret_cast<float4*>(&C[crow + col])     = make_float4(vals[0], vals[1], vals[2], vals[3]);
                    *reinterpret_cast<float4*>(&C[crow + col + 4]) = make_float4(vals[4], vals[5], vals[6], vals[7]);
                }
            }
            TCG_FENCE_BEFORE();
            if (elect_one()) MBAR_ARRIVE(epiDone_[it & 1]);
        }
    }

    __syncthreads();
    CLUSTER_SYNC();                     // peer multicasts fully consumed
    if (tid == 0) {
        #pragma unroll
        for (int i = 0; i < 19; ++i) MBAR_INVAL(smem_u32(&s_mbar[i]));
    }
    __syncthreads();
    if (wid == 0) { TCG_RELINQ(); TCG_DEALLOC(tmem, 512); }
    CLUSTER_SYNC();
#endif // HAS_TCGEN05
}

// ---------------- softmax: g_scores row -> g_p hi/lo bf16 ------------------
__global__ __launch_bounds__(256)
void softmax_kernel()
{
    __shared__ float red[33];
    const size_t row = blockIdx.x;
    const float* p = g_scores + row * (size_t)TK;
    const int tid = threadIdx.x, lane = tid & 31, warp = tid >> 5;

    float4 v0 = *reinterpret_cast<const float4*>(&p[tid * 4]);
    float4 v1 = *reinterpret_cast<const float4*>(&p[1024 + tid * 4]);

    float m = fmaxf(fmaxf(fmaxf(v0.x, v0.y), fmaxf(v0.z, v0.w)),
                    fmaxf(fmaxf(v1.x, v1.y), fmaxf(v1.z, v1.w)));
    #pragma unroll
    for (int o = 16; o; o >>= 1) m = fmaxf(m, __shfl_xor_sync(0xffffffffu, m, o));
    if (lane == 0) red[warp] = m;
    __syncthreads();
    if (tid == 0) {
        float mm = red[0];
        #pragma unroll
        for (int i = 1; i < 8; ++i) mm = fmaxf(mm, red[i]);
        red[32] = mm;
    }
    __syncthreads();
    m = red[32];
    __syncthreads();

    v0.x = __expf(v0.x - m); v0.y = __expf(v0.y - m);
    v0.z = __expf(v0.z - m); v0.w = __expf(v0.w - m);
    v1.x = __expf(v1.x - m); v1.y = __expf(v1.y - m);
    v1.z = __expf(v1.z - m); v1.w = __expf(v1.w - m);

    float s = ((v0.x + v0.y) + (v0.z + v0.w)) + ((v1.x + v1.y) + (v1.z + v1.w));
    #pragma unroll
    for (int o = 16; o; o >>= 1) s += __shfl_xor_sync(0xffffffffu, s, o);
    if (lane == 0) red[warp] = s;
    __syncthreads();
    if (tid == 0) {
        float ss = red[0];
        #pragma unroll
        for (int i = 1; i < 8; ++i) ss += red[i];
        red[32] = ss;
    }
    __syncthreads();
    const float inv = 1.0f / red[32];

    float q0[4] = {v0.x * inv, v0.y * inv, v0.z * inv, v0.w * inv};
    float q1[4] = {v1.x * inv, v1.y * inv, v1.z * inv, v1.w * inv};

    __nv_bfloat16 h[4], l[4];
    const size_t base = row * (size_t)TK;
    #pragma unroll
    for (int j = 0; j < 4; ++j) split2(q0[j], h[j], l[j]);
    *reinterpret_cast<uint2*>(&g_p[0][base + tid * 4]) = *reinterpret_cast<uint2*>(h);
    *reinterpret_cast<uint2*>(&g_p[1][base + tid * 4]) = *reinterpret_cast<uint2*>(l);
    #pragma unroll
    for (int j = 0; j < 4; ++j) split2(q1[j], h[j], l[j]);
    *reinterpret_cast<uint2*>(&g_p[0][base + 1024 + tid * 4]) = *reinterpret_cast<uint2*>(h);
    *reinterpret_cast<uint2*>(&g_p[1][base + 1024 + tid * 4]) = *reinterpret_cast<uint2*>(l);
}

// ---------------- host: tensormap construction ----------------------------
static CUtensorMap h_maps[8];   // qa0 qa1 kb0 kb1 | pa0 pa1 vb0 vb1
static bool        h_maps_ready = false;

typedef CUresult (*pfn_encode_t)(
    CUtensorMap*, CUtensorMapDataType, cuuint32_t, void*,
    const cuuint64_t*, const cuuint64_t*, const cuuint32_t*, const cuuint32_t*,
    CUtensorMapInterleave, CUtensorMapSwizzle, CUtensorMapL2promotion,
    CUtensorMapFloatOOBfill);

static void encode_map(pfn_encode_t enc, CUtensorMap* out, void* base,
                       uint64_t cols, uint64_t rows, uint32_t box_rows)
{
    cuuint64_t dims[2]    = {cols, rows};
    cuuint64_t strides[1] = {cols * 2};           // bf16
    cuuint32_t box[2]     = {64u, box_rows};      // 64 bf16 = 128B (SW128 limit)
    cuuint32_t es[2]      = {1u, 1u};
    enc(out, CU_TENSOR_MAP_DATA_TYPE_BFLOAT16, 2, base, dims, strides, box, es,
        CU_TENSOR_MAP_INTERLEAVE_NONE, CU_TENSOR_MAP_SWIZZLE_128B,
        CU_TENSOR_MAP_L2_PROMOTION_L2_128B, CU_TENSOR_MAP_FLOAT_OOB_FILL_NONE);
}

static void build_maps()
{
    if (h_maps_ready) return;
    pfn_encode_t enc = nullptr;
    cudaDriverEntryPointQueryResult qres;
    cudaGetDriverEntryPointByVersion("cuTensorMapEncodeTiled", (void**)&enc,
                                     12000, cudaEnableDefault, &qres);
    void *pq, *pk, *pv, *pp;
    cudaGetSymbolAddress(&pq, g_qs);
    cudaGetSymbolAddress(&pk, g_ks);
    cudaGetSymbolAddress(&pv, g_vt);
    cudaGetSymbolAddress(&pp, g_p);

    const size_t NQ = (size_t)NB * TQ * DD;
    const size_t NKV = (size_t)NB * DD * TK;
    const size_t NPl = (size_t)NB * TQ * TK;

    encode_map(enc, &h_maps[0], (char*)pq,              DD, (uint64_t)NB * TQ, 128);
    encode_map(enc, &h_maps[1], (char*)pq + NQ * 2,     DD, (uint64_t)NB * TQ, 128);
    encode_map(enc, &h_maps[2], (char*)pk,              DD, (uint64_t)NB * TK, 128);
    encode_map(enc, &h_maps[3], (char*)pk + NQ * 2,     DD, (uint64_t)NB * TK, 128);
    encode_map(enc, &h_maps[4], (char*)pp,              TK, (uint64_t)NB * TQ, 128);
    encode_map(enc, &h_maps[5], (char*)pp + NPl * 2,    TK, (uint64_t)NB * TQ, 128);
    encode_map(enc, &h_maps[6], (char*)pv,              TK, (uint64_t)NB * DD, 128);
    encode_map(enc, &h_maps[7], (char*)pv + NKV * 2,    TK, (uint64_t)NB * DD, 128);
    h_maps_ready = true;
}

// ---------------------------------------------------------------------------
extern "C" void kernel_launch(void* const* d_in, const int* in_sizes, int n_in,
                              void* d_out, int out_size)
{
    const float* q    = (const float*)d_in[0];
    const float* k    = (const float*)d_in[1];
    const float* v    = (const float*)d_in[2];
    const void*  mask = d_in[3];
    float*       out  = (float*)d_out;

    build_maps();

    constexpr int SMEM = 7 * 32768 + 1024;   // 230400
    cudaFuncSetAttribute(mma_gemm_kernel<0>, cudaFuncAttributeMaxDynamicSharedMemorySize, SMEM);
    cudaFuncSetAttribute(mma_gemm_kernel<1>, cudaFuncAttributeMaxDynamicSharedMemorySize, SMEM);

    // conversions
    split_q_kernel<<<(int)(((size_t)NB * TQ * DD / 4) / 256), 256>>>(q);
    tsplit_k_kernel<<<dim3(TK / 32, DD / 32, NB), dim3(32, 8)>>>(k);
    tsplit_v_kernel<<<dim3(DD / 32, TK / 32, NB), dim3(32, 8)>>>(v);

    // scores = q @ k^T (+mask) — persistent 148 CTAs (74 clusters of 2)
    mma_gemm_kernel<0><<<148, 384, SMEM>>>(
        h_maps[0], h_maps[1], h_maps[2], h_maps[3], mask, nullptr);
    // softmax + P split
    softmax_kernel<<<NB * TQ, 256>>>();
    // out = P @ v^T — persistent 148 CTAs (74 clusters of 2)
    mma_gemm_kernel<1><<<148, 384, SMEM>>>(
        h_maps[4], h_maps[5], h_maps[6], h_maps[7], nullptr, out);
}

// round 17
// speedup vs baseline: 1.0800x; 1.0800x over previous
#include <cuda_runtime.h>
#include <cuda_bf16.h>
#include <cuda.h>
#include <stdint.h>

#define NB 16
#define TQ 2048
#define TK 2048
#define DD 1024

#if defined(__CUDA_ARCH__) && defined(__CUDA_ARCH_FEAT_SM103_ALL)
#define HAS_TCGEN05 1
#else
#define HAS_TCGEN05 0
#endif

// ---------------- scratch (static __device__ arrays; no runtime alloc) ----
__device__ float         g_scores[(size_t)NB * TQ * TK];    // masked logits
__device__ __nv_bfloat16 g_qs[2][(size_t)NB * TQ * DD];     // q hi/lo       [b][tq][d]
__device__ __nv_bfloat16 g_ks[2][(size_t)NB * TK * DD];     // k^T hi/lo     [b][tk][d]
__device__ __nv_bfloat16 g_vt[2][(size_t)NB * DD * TK];     // v^T hi/lo     [b][d][tk]
__device__ __nv_bfloat16 g_p [2][(size_t)NB * TQ * TK];     // softmax hi/lo [b][tq][tk]

__device__ __forceinline__ uint32_t smem_u32(const void* p) {
    uint32_t a;
    asm("{ .reg .u64 t; cvta.to.shared.u64 t, %1; cvt.u32.u64 %0, t; }" : "=r"(a) : "l"(p));
    return a;
}

#define MASK_BYTES 0
#define MASK_WORDS 1
__device__ __forceinline__ int detect_mask_kind(const void* mask) {
    const uint32_t* w = (const uint32_t*)mask;
    bool all01 = true, all0f = true;
    #pragma unroll 8
    for (int i = 0; i < 64; ++i) {
        uint32_t x = w[i];
        all01 &= (x <= 1u);
        all0f &= (x == 0u || x == 0x3F800000u);
    }
    return (all01 || all0f) ? MASK_WORDS : MASK_BYTES;
}

__device__ __forceinline__ void split2(float x, __nv_bfloat16& a0, __nv_bfloat16& a1) {
    a0 = __float2bfloat16(x);
    a1 = __float2bfloat16(x - __bfloat162float(a0));
}

// ---------------- sm_103a-only PTX wrappers --------------------------------
#if HAS_TCGEN05
__device__ __forceinline__ uint32_t elect_one() {
    uint32_t pred;
    asm volatile("{ .reg .pred p; elect.sync _|p, 0xFFFFFFFF; selp.b32 %0, 1, 0, p; }" : "=r"(pred));
    return pred;
}
#define TCG_ALLOC(sa, n)  asm volatile("tcgen05.alloc.cta_group::1.sync.aligned.shared::cta.b32 [%0], %1;" :: "r"(sa), "r"(n) : "memory")
#define TCG_DEALLOC(t, n) asm volatile("tcgen05.dealloc.cta_group::1.sync.aligned.b32 %0, %1;" :: "r"(t), "r"(n))
#define TCG_RELINQ()      asm volatile("tcgen05.relinquish_alloc_permit.cta_group::1.sync.aligned;")
#define TCG_COMMIT(mb)    asm volatile("tcgen05.commit.cta_group::1.mbarrier::arrive::one.shared::cluster.b64 [%0];" :: "r"(mb) : "memory")
#define TCG_FENCE_AFTER()  asm volatile("tcgen05.fence::after_thread_sync;" ::: "memory")
#define TCG_FENCE_BEFORE() asm volatile("tcgen05.fence::before_thread_sync;" ::: "memory")
#define TCG_WAIT_LD()      asm volatile("tcgen05.wait::ld.sync.aligned;" ::: "memory")
#define MBAR_INIT(mb, n)   asm volatile("mbarrier.init.shared.b64 [%0], %1;" :: "r"(mb), "r"(n) : "memory")
#define MBAR_INVAL(mb)     asm volatile("mbarrier.inval.shared.b64 [%0];" :: "r"(mb) : "memory")
#define MBAR_ARRIVE(mb)    asm volatile("mbarrier.arrive.shared.b64 _, [%0];" :: "r"(mb) : "memory")
#define MBAR_EXPECT_TX(mb, n) asm volatile("mbarrier.arrive.expect_tx.shared.b64 _, [%0], %1;" :: "r"(mb), "r"(n) : "memory")
#define FENCE_ASYNC_SHARED() asm volatile("fence.proxy.async.shared::cta;" ::: "memory")

#define TMA_LOAD_2D(smem, map, x, y, mbar)                                   \
    asm volatile("cp.async.bulk.tensor.2d.shared::cta.global.tile.mbarrier::complete_tx::bytes " \
                 "[%0], [%1, {%2, %3}], [%4];"                               \
                 :: "r"(smem), "l"(map), "r"(x), "r"(y), "r"(mbar) : "memory")

#define MBAR_WAIT(mb, par) do {                                              \
    uint32_t _m = (mb), _p = (par), _d;                                      \
    asm volatile("{ .reg .pred p; mbarrier.try_wait.parity.acquire.cta.shared::cta.b64 p, [%1], %2; selp.b32 %0,1,0,p; }" \
                 : "=r"(_d) : "r"(_m), "r"(_p) : "memory");                  \
    if (!_d) {                                                               \
        asm volatile("{ .reg .pred P1; WL_%=: mbarrier.try_wait.parity.acquire.cta.shared::cta.b64 P1, [%0], %1, 0x989680; \n\t" \
                     "@P1 bra.uni WD_%=; bra.uni WL_%=; WD_%=: }"            \
                     :: "r"(_m), "r"(_p) : "memory");                        \
    }                                                                        \
} while (0)

#define TCG_LD_X32(r, ta)                                                    \
    asm volatile("tcgen05.ld.sync.aligned.32x32b.x32.b32 "                   \
        "{%0,%1,%2,%3,%4,%5,%6,%7,%8,%9,%10,%11,%12,%13,%14,%15,"            \
        "%16,%17,%18,%19,%20,%21,%22,%23,%24,%25,%26,%27,%28,%29,%30,%31}, [%32];" \
        : "=r"((r)[0]),"=r"((r)[1]),"=r"((r)[2]),"=r"((r)[3]),               \
          "=r"((r)[4]),"=r"((r)[5]),"=r"((r)[6]),"=r"((r)[7]),               \
          "=r"((r)[8]),"=r"((r)[9]),"=r"((r)[10]),"=r"((r)[11]),             \
          "=r"((r)[12]),"=r"((r)[13]),"=r"((r)[14]),"=r"((r)[15]),           \
          "=r"((r)[16]),"=r"((r)[17]),"=r"((r)[18]),"=r"((r)[19]),           \
          "=r"((r)[20]),"=r"((r)[21]),"=r"((r)[22]),"=r"((r)[23]),           \
          "=r"((r)[24]),"=r"((r)[25]),"=r"((r)[26]),"=r"((r)[27]),           \
          "=r"((r)[28]),"=r"((r)[29]),"=r"((r)[30]),"=r"((r)[31])            \
        : "r"(ta))

__device__ __forceinline__ void mma_f16_ss(uint32_t d_tmem, uint64_t a_desc,
                                           uint64_t b_desc, uint32_t idesc,
                                           uint32_t enable_d) {
    asm volatile(
        "{\n\t.reg .pred p;\n\tsetp.ne.u32 p, %5, 0;\n\t"
        "tcgen05.mma.cta_group::1.kind::f16 [%0], %1, %2, %3, {%4, %4, %4, %4}, p;\n\t}"
        :: "r"(d_tmem), "l"(a_desc), "l"(b_desc), "r"(idesc), "r"(0u), "r"(enable_d)
        : "memory");
}

static constexpr uint64_t DESC_BASE_SW128 =
    (uint64_t(2) << 61) | (uint64_t(1) << 46) | (uint64_t(64) << 32) | (uint64_t(1) << 16);
__device__ __forceinline__ uint64_t mk_desc(uint32_t addr) {
    return DESC_BASE_SW128 | ((uint64_t)(addr >> 4) & 0x3FFF);
}
#endif // HAS_TCGEN05

// idesc: dtype F32, atype/btype BF16, N=128, M=128 (validated formula)
static constexpr uint32_t IDESC_128x128 =
    (1u << 4) | (1u << 7) | (1u << 10) | ((128u / 8) << 17) | ((128u / 16) << 24);

// ---------------- conversion pre-passes ------------------------------------
__global__ __launch_bounds__(256) void split_q_kernel(const float* __restrict__ q) {
    size_t i = ((size_t)blockIdx.x * 256 + threadIdx.x) * 4;
    float4 x = *reinterpret_cast<const float4*>(q + i);
    __nv_bfloat16 a0[4], a1[4];
    split2(x.x, a0[0], a1[0]);
    split2(x.y, a0[1], a1[1]);
    split2(x.z, a0[2], a1[2]);
    split2(x.w, a0[3], a1[3]);
    *reinterpret_cast<uint2*>(&g_qs[0][i]) = *reinterpret_cast<uint2*>(a0);
    *reinterpret_cast<uint2*>(&g_qs[1][i]) = *reinterpret_cast<uint2*>(a1);
}

// k[b][d][t] -> g_ks[s][b][t][d]
__global__ __launch_bounds__(256) void tsplit_k_kernel(const float* __restrict__ k) {
    __shared__ float tile[32][33];
    const int b = blockIdx.z, d0 = blockIdx.y * 32, t0 = blockIdx.x * 32;
    const int tx = threadIdx.x, ty = threadIdx.y;
    const float* src = k + ((size_t)b * DD + d0) * TK + t0;
    #pragma unroll
    for (int j = 0; j < 32; j += 8) tile[ty + j][tx] = src[(size_t)(ty + j) * TK + tx];
    __syncthreads();
    const size_t obase = ((size_t)b * TK + t0) * DD + d0;
    #pragma unroll
    for (int j = 0; j < 32; j += 8) {
        float x = tile[tx][ty + j];
        __nv_bfloat16 a0, a1;
        split2(x, a0, a1);
        size_t o = obase + (size_t)(ty + j) * DD + tx;
        g_ks[0][o] = a0; g_ks[1][o] = a1;
    }
}

// v[b][t][d] -> g_vt[s][b][d][t]
__global__ __launch_bounds__(256) void tsplit_v_kernel(const float* __restrict__ v) {
    __shared__ float tile[32][33];
    const int b = blockIdx.z, d0 = blockIdx.x * 32, t0 = blockIdx.y * 32;
    const int tx = threadIdx.x, ty = threadIdx.y;
    const float* src = v + ((size_t)b * TK + t0) * DD + d0;
    #pragma unroll
    for (int j = 0; j < 32; j += 8) tile[ty + j][tx] = src[(size_t)(ty + j) * DD + tx];
    __syncthreads();
    const size_t obase = ((size_t)b * DD + d0) * TK + t0;
    #pragma unroll
    for (int j = 0; j < 32; j += 8) {
        float x = tile[tx][ty + j];
        __nv_bfloat16 a0, a1;
        split2(x, a0, a1);
        size_t o = obase + (size_t)(ty + j) * TK + tx;
        g_vt[0][o] = a0; g_vt[1][o] = a1;
    }
}

// ---------------- persistent warp-specialized tcgen05 GEMM -----------------
// MODE 0: scores = q @ k^T (3-term split: q0k0+q0k1+q1k0) + mask -> g_scores
//         (the q1*k1 term contributes ~1e-4 rel err and is dropped: the
//          tensor unit is saturated, so fewer MMAs = proportionally faster)
// MODE 1: out    = P @ v^T (3-term split) -> d_out
//
// 148 persistent CTAs x 384 threads; tiles t = bx + i*148 (128x256 output).
// Rings (B 4x32K, A 3x32K) persist across tiles. TMEM double-buffered so
// warps 4-11 drain tile i's epilogue while warp 0 runs tile i+1's MMAs and
// warp 1 keeps the TMA rings full. (Structure = R15 baseline.)
template<int MODE>
__global__ __launch_bounds__(384, 1)
void mma_gemm_kernel(const __grid_constant__ CUtensorMap ta0,
                     const __grid_constant__ CUtensorMap ta1,
                     const __grid_constant__ CUtensorMap tb0,
                     const __grid_constant__ CUtensorMap tb1,
                     const void* __restrict__ mask, float* __restrict__ Zout)
{
#if HAS_TCGEN05
    constexpr int NP     = 3;                            // both GEMMs 3 terms
    constexpr int KTOT   = (MODE == 0) ? DD : TK;
    constexpr int NCH    = KTOT / 64;
    constexpr int NST    = 2 * NCH;
    constexpr int LDC    = (MODE == 0) ? TK : DD;
    constexpr int RB     = (MODE == 0) ? TK : DD;
    constexpr int LOG_NX = (MODE == 0) ? 3 : 2;          // tiles along N
    constexpr int NTILES = (MODE == 0) ? (NB * 16 * 8) : (NB * 16 * 4);
    constexpr uint32_t SSZ  = 32768u;
    constexpr uint32_t AOFF = 4u * SSZ;

    const int PA[3] = {0, 0, 1};
    const int PB[3] = {0, 1, 0};

    extern __shared__ char dsm[];
    __shared__ uint64_t s_mbar[15];   // fullB[4], mmaB[4], fullA[3], tileDone[2], epiDone[2]
    __shared__ uint32_t s_tmem;
    __shared__ int      s_mkind;

    const int tid = threadIdx.x;
    const int wid = tid >> 5, lid = tid & 31;
    const int bx  = blockIdx.x;
    const int G   = gridDim.x;
    const int nt  = (NTILES - bx + G - 1) / G;           // tiles for this CTA

    const uint32_t su   = smem_u32(dsm);
    const uint32_t pad  = (1024u - (su & 1023u)) & 1023u;
    const uint32_t sb_u = su + pad;

    uint32_t fullB_[4], mmaB_[4], fullA_[3], tileDone_[2], epiDone_[2];
    #pragma unroll
    for (int i = 0; i < 4; ++i) { fullB_[i] = smem_u32(&s_mbar[i]); mmaB_[i] = smem_u32(&s_mbar[4 + i]); }
    #pragma unroll
    for (int i = 0; i < 3; ++i) fullA_[i] = smem_u32(&s_mbar[8 + i]);
    #pragma unroll
    for (int i = 0; i < 2; ++i) { tileDone_[i] = smem_u32(&s_mbar[11 + i]); epiDone_[i] = smem_u32(&s_mbar[13 + i]); }

    if (wid == 0) TCG_ALLOC(smem_u32(&s_tmem), 512);
    if (tid == 0) {
        #pragma unroll
        for (int i = 0; i < 13; ++i) MBAR_INIT(smem_u32(&s_mbar[i]), 1);
        MBAR_INIT(epiDone_[0], 8);
        MBAR_INIT(epiDone_[1], 8);
        FENCE_ASYNC_SHARED();
        if (MODE == 0) s_mkind = detect_mask_kind(mask);
    }
    __syncthreads();
    const uint32_t tmem = s_tmem;

    if (wid == 1 && elect_one()) {
        // ====================== producer warp ======================
        {
            const int t0 = bx;
            const int y0 = (t0 >> LOG_NX) & 15, b0 = t0 >> (LOG_NX + 4);
            const int x0 = t0 & ((1 << LOG_NX) - 1);
            const int rA0 = b0 * TQ + y0 * 128;
            const int rB0 = b0 * RB + x0 * 256;
            #pragma unroll
            for (int j = 0; j < 3; ++j) {
                const uint32_t sa = sb_u + AOFF + j * SSZ;
                MBAR_EXPECT_TX(fullA_[j], SSZ);
                TMA_LOAD_2D(sa,           &ta0, j * 64, rA0, fullA_[j]);
                TMA_LOAD_2D(sa + 16384u,  &ta1, j * 64, rA0, fullA_[j]);
            }
            #pragma unroll
            for (int i = 0; i < 4; ++i) {
                const uint32_t sbb = sb_u + i * SSZ;
                MBAR_EXPECT_TX(fullB_[i], SSZ);
                TMA_LOAD_2D(sbb,          &tb0, (i >> 1) * 64, rB0 + (i & 1) * 128, fullB_[i]);
                TMA_LOAD_2D(sbb + 16384u, &tb1, (i >> 1) * 64, rB0 + (i & 1) * 128, fullB_[i]);
            }
        }
        const int NSTtot = nt * NST;
        const int NCHtot = nt * NCH;
        for (int S2 = 0; S2 < NSTtot - 4; ++S2) {
            MBAR_WAIT(mmaB_[S2 & 3], (S2 >> 2) & 1);
            {   // refill B for global step S2+4
                const int Sg = S2 + 4;
                const int it = Sg / NST, s = Sg % NST;
                const int t = bx + it * G;
                const int x = t & ((1 << LOG_NX) - 1);
                const int bb = t >> (LOG_NX + 4);
                const int rBv = bb * RB + x * 256 + (s & 1) * 128;
                const uint32_t dst = sb_u + (uint32_t)(Sg & 3) * SSZ;
                MBAR_EXPECT_TX(fullB_[Sg & 3], SSZ);
                TMA_LOAD_2D(dst,          &tb0, (s >> 1) * 64, rBv, fullB_[Sg & 3]);
                TMA_LOAD_2D(dst + 16384u, &tb1, (s >> 1) * 64, rBv, fullB_[Sg & 3]);
            }
            if ((S2 & 1) == 1) {
                const int Cg = (S2 >> 1) + 3;
                if (Cg < NCHtot) {
                    const int it = Cg / NCH, cl = Cg % NCH;
                    const int t = bx + it * G;
                    const int y = (t >> LOG_NX) & 15, bb = t >> (LOG_NX + 4);
                    const int rAv = bb * TQ + y * 128;
                    const uint32_t dst = sb_u + AOFF + (uint32_t)(Cg % 3) * SSZ;
                    MBAR_EXPECT_TX(fullA_[Cg % 3], SSZ);
                    TMA_LOAD_2D(dst,           &ta0, cl * 64, rAv, fullA_[Cg % 3]);
                    TMA_LOAD_2D(dst + 16384u,  &ta1, cl * 64, rAv, fullA_[Cg % 3]);
                }
            }
        }
    }

    if (wid == 0 && elect_one()) {
        // ====================== MMA consumer warp ======================
        for (int it = 0; it < nt; ++it) {
            const uint32_t dOff = (uint32_t)(it & 1) * 256u;
            if (it >= 2) MBAR_WAIT(epiDone_[it & 1], ((it >> 1) - 1) & 1);
            for (int s = 0; s < NST; ++s) {
                const int c = s >> 1, h = s & 1;
                const int Sg = it * NST + s;
                const int Cg = it * NCH + c;
                const uint32_t aBase = sb_u + AOFF + (uint32_t)(Cg % 3) * SSZ;
                const uint32_t bBase = sb_u + (uint32_t)(Sg & 3) * SSZ;

                if (h == 0) MBAR_WAIT(fullA_[Cg % 3], (Cg / 3) & 1);
                MBAR_WAIT(fullB_[Sg & 3], (Sg >> 2) & 1);

                #pragma unroll
                for (int pi = 0; pi < NP; ++pi) {
                    const uint64_t ad = mk_desc(aBase + (uint32_t)PA[pi] * 16384u);
                    const uint64_t bd = mk_desc(bBase + (uint32_t)PB[pi] * 16384u);
                    #pragma unroll
                    for (int g = 0; g < 4; ++g)
                        mma_f16_ss(tmem + dOff + h * 128, ad + 2 * g, bd + 2 * g,
                                   IDESC_128x128, !(c == 0 && pi == 0 && g == 0));
                }
                TCG_COMMIT(mmaB_[Sg & 3]);
            }
            TCG_COMMIT(tileDone_[it & 1]);
        }
    }

    if (wid >= 4) {
        // ====================== epilogue warps (8) ======================
        const int row  = (wid & 3) * 32 + lid;
        const int coff = ((wid >> 2) - 1) * 128;
        const int mkind = (MODE == 0) ? s_mkind : 0;

        for (int it = 0; it < nt; ++it) {
            const uint32_t dOff = (uint32_t)(it & 1) * 256u;
            MBAR_WAIT(tileDone_[it & 1], (it >> 1) & 1);
            TCG_FENCE_AFTER();

            const int t = bx + it * G;
            const int x = t & ((1 << LOG_NX) - 1);
            const int y = (t >> LOG_NX) & 15, bb = t >> (LOG_NX + 4);
            const int mBase = y * 128, nBase = x * 256;

            float* C = (MODE == 0) ? (g_scores + (size_t)bb * TQ * TK)
                                   : (Zout + (size_t)bb * TQ * DD);
            const size_t crow = (size_t)(mBase + row) * LDC + nBase + coff;
            const size_t erow = (MODE == 0)
                ? (((size_t)bb * TQ + mBase + row) * TK + nBase + coff) : 0;

            #pragma unroll
            for (int cc = 0; cc < 4; ++cc) {
                uint32_t r[32];
                TCG_LD_X32(r, tmem + dOff + coff + cc * 32);
                TCG_WAIT_LD();
                #pragma unroll
                for (int g = 0; g < 4; ++g) {
                    float vals[8];
                    #pragma unroll
                    for (int j = 0; j < 8; ++j) vals[j] = __uint_as_float(r[g * 8 + j]);
                    const int col = cc * 32 + g * 8;
                    if (MODE == 0) {
                        const size_t eidx = erow + col;
                        bool mk[8];
                        if (mkind == MASK_BYTES) {
                            unsigned long long mv =
                                *reinterpret_cast<const unsigned long long*>((const uint8_t*)mask + eidx);
                            #pragma unroll
                            for (int j = 0; j < 8; ++j) mk[j] = ((mv >> (8 * j)) & 0xffULL) != 0;
                        } else {
                            const uint32_t* mw = (const uint32_t*)mask + eidx;
                            uint4 w0 = *reinterpret_cast<const uint4*>(mw);
                            uint4 w1 = *reinterpret_cast<const uint4*>(mw + 4);
                            mk[0] = w0.x != 0; mk[1] = w0.y != 0; mk[2] = w0.z != 0; mk[3] = w0.w != 0;
                            mk[4] = w1.x != 0; mk[5] = w1.y != 0; mk[6] = w1.z != 0; mk[7] = w1.w != 0;
                        }
                        #pragma unroll
                        for (int j = 0; j < 8; ++j)
                            if (mk[j]) vals[j] = -1.0e9f;
                    }
                    *reinterpret_cast<float4*>(&C[crow + col])     = make_float4(vals[0], vals[1], vals[2], vals[3]);
                    *reinterpret_cast<float4*>(&C[crow + col + 4]) = make_float4(vals[4], vals[5], vals[6], vals[7]);
                }
            }
            TCG_FENCE_BEFORE();
            if (elect_one()) MBAR_ARRIVE(epiDone_[it & 1]);
        }
    }

    __syncthreads();
    if (tid == 0) {
        #pragma unroll
        for (int i = 0; i < 15; ++i) MBAR_INVAL(smem_u32(&s_mbar[i]));
    }
    __syncthreads();
    if (wid == 0) { TCG_RELINQ(); TCG_DEALLOC(tmem, 512); }
#endif // HAS_TCGEN05
}

// ---------------- softmax: g_scores row -> g_p hi/lo bf16 ------------------
__global__ __launch_bounds__(256)
void softmax_kernel()
{
    __shared__ float red[33];
    const size_t row = blockIdx.x;
    const float* p = g_scores + row * (size_t)TK;
    const int tid = threadIdx.x, lane = tid & 31, warp = tid >> 5;

    float4 v0 = *reinterpret_cast<const float4*>(&p[tid * 4]);
    float4 v1 = *reinterpret_cast<const float4*>(&p[1024 + tid * 4]);

    float m = fmaxf(fmaxf(fmaxf(v0.x, v0.y), fmaxf(v0.z, v0.w)),
                    fmaxf(fmaxf(v1.x, v1.y), fmaxf(v1.z, v1.w)));
    #pragma unroll
    for (int o = 16; o; o >>= 1) m = fmaxf(m, __shfl_xor_sync(0xffffffffu, m, o));
    if (lane == 0) red[warp] = m;
    __syncthreads();
    if (tid == 0) {
        float mm = red[0];
        #pragma unroll
        for (int i = 1; i < 8; ++i) mm = fmaxf(mm, red[i]);
        red[32] = mm;
    }
    __syncthreads();
    m = red[32];
    __syncthreads();

    v0.x = __expf(v0.x - m); v0.y = __expf(v0.y - m);
    v0.z = __expf(v0.z - m); v0.w = __expf(v0.w - m);
    v1.x = __expf(v1.x - m); v1.y = __expf(v1.y - m);
    v1.z = __expf(v1.z - m); v1.w = __expf(v1.w - m);

    float s = ((v0.x + v0.y) + (v0.z + v0.w)) + ((v1.x + v1.y) + (v1.z + v1.w));
    #pragma unroll
    for (int o = 16; o; o >>= 1) s += __shfl_xor_sync(0xffffffffu, s, o);
    if (lane == 0) red[warp] = s;
    __syncthreads();
    if (tid == 0) {
        float ss = red[0];
        #pragma unroll
        for (int i = 1; i < 8; ++i) ss += red[i];
        red[32] = ss;
    }
    __syncthreads();
    const float inv = 1.0f / red[32];

    float q0[4] = {v0.x * inv, v0.y * inv, v0.z * inv, v0.w * inv};
    float q1[4] = {v1.x * inv, v1.y * inv, v1.z * inv, v1.w * inv};

    __nv_bfloat16 h[4], l[4];
    const size_t base = row * (size_t)TK;
    #pragma unroll
    for (int j = 0; j < 4; ++j) split2(q0[j], h[j], l[j]);
    *reinterpret_cast<uint2*>(&g_p[0][base + tid * 4]) = *reinterpret_cast<uint2*>(h);
    *reinterpret_cast<uint2*>(&g_p[1][base + tid * 4]) = *reinterpret_cast<uint2*>(l);
    #pragma unroll
    for (int j = 0; j < 4; ++j) split2(q1[j], h[j], l[j]);
    *reinterpret_cast<uint2*>(&g_p[0][base + 1024 + tid * 4]) = *reinterpret_cast<uint2*>(h);
    *reinterpret_cast<uint2*>(&g_p[1][base + 1024 + tid * 4]) = *reinterpret_cast<uint2*>(l);
}

// ---------------- host: tensormap construction ----------------------------
static CUtensorMap h_maps[8];   // qa0 qa1 kb0 kb1 | pa0 pa1 vb0 vb1
static bool        h_maps_ready = false;

typedef CUresult (*pfn_encode_t)(
    CUtensorMap*, CUtensorMapDataType, cuuint32_t, void*,
    const cuuint64_t*, const cuuint64_t*, const cuuint32_t*, const cuuint32_t*,
    CUtensorMapInterleave, CUtensorMapSwizzle, CUtensorMapL2promotion,
    CUtensorMapFloatOOBfill);

static void encode_map(pfn_encode_t enc, CUtensorMap* out, void* base,
                       uint64_t cols, uint64_t rows, uint32_t box_rows)
{
    cuuint64_t dims[2]    = {cols, rows};
    cuuint64_t strides[1] = {cols * 2};           // bf16
    cuuint32_t box[2]     = {64u, box_rows};      // 64 bf16 = 128B (SW128 limit)
    cuuint32_t es[2]      = {1u, 1u};
    enc(out, CU_TENSOR_MAP_DATA_TYPE_BFLOAT16, 2, base, dims, strides, box, es,
        CU_TENSOR_MAP_INTERLEAVE_NONE, CU_TENSOR_MAP_SWIZZLE_128B,
        CU_TENSOR_MAP_L2_PROMOTION_L2_128B, CU_TENSOR_MAP_FLOAT_OOB_FILL_NONE);
}

static void build_maps()
{
    if (h_maps_ready) return;
    pfn_encode_t enc = nullptr;
    cudaDriverEntryPointQueryResult qres;
    cudaGetDriverEntryPointByVersion("cuTensorMapEncodeTiled", (void**)&enc,
                                     12000, cudaEnableDefault, &qres);
    void *pq, *pk, *pv, *pp;
    cudaGetSymbolAddress(&pq, g_qs);
    cudaGetSymbolAddress(&pk, g_ks);
    cudaGetSymbolAddress(&pv, g_vt);
    cudaGetSymbolAddress(&pp, g_p);

    const size_t NQ = (size_t)NB * TQ * DD;
    const size_t NKV = (size_t)NB * DD * TK;
    const size_t NPl = (size_t)NB * TQ * TK;

    encode_map(enc, &h_maps[0], (char*)pq,              DD, (uint64_t)NB * TQ, 128);
    encode_map(enc, &h_maps[1], (char*)pq + NQ * 2,     DD, (uint64_t)NB * TQ, 128);
    encode_map(enc, &h_maps[2], (char*)pk,              DD, (uint64_t)NB * TK, 128);
    encode_map(enc, &h_maps[3], (char*)pk + NQ * 2,     DD, (uint64_t)NB * TK, 128);
    encode_map(enc, &h_maps[4], (char*)pp,              TK, (uint64_t)NB * TQ, 128);
    encode_map(enc, &h_maps[5], (char*)pp + NPl * 2,    TK, (uint64_t)NB * TQ, 128);
    encode_map(enc, &h_maps[6], (char*)pv,              TK, (uint64_t)NB * DD, 128);
    encode_map(enc, &h_maps[7], (char*)pv + NKV * 2,    TK, (uint64_t)NB * DD, 128);
    h_maps_ready = true;
}

// ---------------------------------------------------------------------------
extern "C" void kernel_launch(void* const* d_in, const int* in_sizes, int n_in,
                              void* d_out, int out_size)
{
    const float* q    = (const float*)d_in[0];
    const float* k    = (const float*)d_in[1];
    const float* v    = (const float*)d_in[2];
    const void*  mask = d_in[3];
    float*       out  = (float*)d_out;

    build_maps();

    constexpr int SMEM = 7 * 32768 + 1024;   // 230400
    cudaFuncSetAttribute(mma_gemm_kernel<0>, cudaFuncAttributeMaxDynamicSharedMemorySize, SMEM);
    cudaFuncSetAttribute(mma_gemm_kernel<1>, cudaFuncAttributeMaxDynamicSharedMemorySize, SMEM);

    // conversions
    split_q_kernel<<<(int)(((size_t)NB * TQ * DD / 4) / 256), 256>>>(q);
    tsplit_k_kernel<<<dim3(TK / 32, DD / 32, NB), dim3(32, 8)>>>(k);
    tsplit_v_kernel<<<dim3(DD / 32, TK / 32, NB), dim3(32, 8)>>>(v);

    // scores = q @ k^T (+mask) — persistent 148 CTAs
    mma_gemm_kernel<0><<<148, 384, SMEM>>>(
        h_maps[0], h_maps[1], h_maps[2], h_maps[3], mask, nullptr);
    // softmax + P split
    softmax_kernel<<<NB * TQ, 256>>>();
    // out = P @ v^T — persistent 148 CTAs
    mma_gemm_kernel<1><<<148, 384, SMEM>>>(
        h_maps[4], h_maps[5], h_maps[6], h_maps[7], nullptr, out);
}